// round 14
// baseline (speedup 1.0000x reference)
#include <cuda_runtime.h>
#include <math.h>
#include <stdint.h>

#define NN 40000
#define NE 640000
#define D 128
#define DC 512
#define NCLS 40
#define SCAN_NB ((NN + 255) / 256)   // 157
#define MT 288                        // GEMM M-tile (9 warp-rows x 32)
#define NT2 ((NN + MT - 1) / MT)      // 139 tiles -> single wave on 148 SMs

// ---------------- device scratch ----------------
__device__ int   g_deg[NN];
__device__ float g_dinv[NN];
__device__ int   g_off[NN + 1];
__device__ int   g_pos[NN];
__device__ int   g_src[NE];
__device__ int   g_bsum[SCAN_NB];
__device__ __align__(16) float g_gbuf[NN * D];        // lin output h (fp32, for gather)
// pre-split bf16 hi/lo planes (u32 = packed bf16x2 pair along k)
__device__ __align__(16) uint32_t g_xh[NN * 64],    g_xl[NN * 64];
__device__ __align__(16) uint32_t g_feath[NN * 256], g_featl[NN * 256];
__device__ __align__(16) uint32_t g_x1h[NN * 64],   g_x1l[NN * 64];
__device__ __align__(16) uint32_t g_w0h[128 * 64],  g_w0l[128 * 64];
__device__ __align__(16) uint32_t g_c0h[128 * 256], g_c0l[128 * 256];
__device__ __align__(16) uint32_t g_w1h[128 * 64],  g_w1l[128 * 64];
__device__ __align__(16) uint32_t g_c1h[128 * 256], g_c1l[128 * 256];

// ---------------- bf16 helpers ----------------
__device__ __forceinline__ void split2(float x0, float x1, uint32_t& hi2, uint32_t& lo2) {
    asm("cvt.rn.bf16x2.f32 %0, %1, %2;" : "=r"(hi2) : "f"(x1), "f"(x0));
    float h0 = __uint_as_float(hi2 << 16);
    float h1 = __uint_as_float(hi2 & 0xffff0000u);
    float l0 = x0 - h0, l1 = x1 - h1;
    asm("cvt.rn.bf16x2.f32 %0, %1, %2;" : "=r"(lo2) : "f"(l1), "f"(l0));
}
__device__ __forceinline__ void mma16(float* c, const uint32_t* a, const uint32_t* b) {
    asm volatile(
        "mma.sync.aligned.m16n8k16.row.col.f32.bf16.bf16.f32 "
        "{%0,%1,%2,%3}, {%4,%5,%6,%7}, {%8,%9}, {%0,%1,%2,%3};"
        : "+f"(c[0]), "+f"(c[1]), "+f"(c[2]), "+f"(c[3])
        : "r"(a[0]), "r"(a[1]), "r"(a[2]), "r"(a[3]), "r"(b[0]), "r"(b[1]));
}
__device__ __forceinline__ uint32_t smem_u32(const void* p) {
    uint32_t a;
    asm("{ .reg .u64 t; cvta.to.shared.u64 t, %1; cvt.u32.u64 %0, t; }" : "=r"(a) : "l"(p));
    return a;
}
#define LDM4(r0, r1, r2, r3, a) \
    asm volatile("ldmatrix.sync.aligned.m8n8.x4.shared.b16 {%0,%1,%2,%3}, [%4];" \
        : "=r"(r0), "=r"(r1), "=r"(r2), "=r"(r3) : "r"(a))
#define CPA(dst, src, sz) \
    asm volatile("cp.async.cg.shared.global [%0], [%1], 16, %2;" \
        :: "r"(dst), "l"(src), "r"(sz))
#define CPA_COMMIT() asm volatile("cp.async.commit_group;" ::: "memory")
#define CPA_WAIT1()  asm volatile("cp.async.wait_group 1;" ::: "memory")

// ---------------- small utilities ----------------
__device__ __forceinline__ int warp_iscan(int v) {
    #pragma unroll
    for (int d = 1; d < 32; d <<= 1) {
        int t = __shfl_up_sync(0xffffffffu, v, d);
        if ((threadIdx.x & 31) >= d) v += t;
    }
    return v;
}

// ---------------- pre-split kernels ----------------
__global__ void k_split_xw0(const float* __restrict__ x, const float* __restrict__ W0) {
    const int i = blockIdx.x * 256 + threadIdx.x;
    const int NW = 128 * 64;
    if (i < NW) {
        uint32_t h, l;
        split2(W0[2 * i], W0[2 * i + 1], h, l);
        g_w0h[i] = h; g_w0l[i] = l;
    }
    const int j = i - NW;
    if (j >= 0 && j < NN * 64) {
        uint32_t h, l;
        split2(x[2 * j], x[2 * j + 1], h, l);
        g_xh[j] = h; g_xl[j] = l;
    }
}
// DST: 0 = C0, 1 = W1, 2 = C1
template <int DST>
__global__ void k_splitw(const float* __restrict__ src, int npairs) {
    const int i = blockIdx.x * 256 + threadIdx.x;
    if (i >= npairs) return;
    uint32_t h, l;
    split2(src[2 * i], src[2 * i + 1], h, l);
    if (DST == 0) { g_c0h[i] = h; g_c0l[i] = l; }
    if (DST == 1) { g_w1h[i] = h; g_w1l[i] = l; }
    if (DST == 2) { g_c1h[i] = h; g_c1l[i] = l; }
}

// ---------------- graph preprocessing ----------------
__global__ void k_init() {
    int i = blockIdx.x * 256 + threadIdx.x;
    if (i < NN) g_deg[i] = 1;
}
__global__ void k_count(const int* __restrict__ ei) {
    int e = blockIdx.x * 256 + threadIdx.x;
    if (e < NE) atomicAdd(&g_deg[ei[NE + e]], 1);
}
__global__ void k_scan_a() {
    __shared__ int wsum[8];
    int i = blockIdx.x * 256 + threadIdx.x;
    int cnt = (i < NN) ? (g_deg[i] - 1) : 0;
    int inc = warp_iscan(cnt);
    int wid = threadIdx.x >> 5, lane = threadIdx.x & 31;
    if (lane == 31) wsum[wid] = inc;
    __syncthreads();
    if (wid == 0) {
        int v = (lane < 8) ? wsum[lane] : 0;
        v = warp_iscan(v);
        if (lane < 8) wsum[lane] = v;
    }
    __syncthreads();
    int base = wid ? wsum[wid - 1] : 0;
    if (i < NN) g_off[i] = base + inc - cnt;
    if (threadIdx.x == 255) g_bsum[blockIdx.x] = base + inc;
}
__global__ void k_scan_b() {
    __shared__ int wsum[8];
    int t = threadIdx.x;
    int v = (t < SCAN_NB) ? g_bsum[t] : 0;
    int inc = warp_iscan(v);
    int wid = t >> 5, lane = t & 31;
    if (lane == 31) wsum[wid] = inc;
    __syncthreads();
    if (wid == 0) {
        int u = (lane < 8) ? wsum[lane] : 0;
        u = warp_iscan(u);
        if (lane < 8) wsum[lane] = u;
    }
    __syncthreads();
    int base = wid ? wsum[wid - 1] : 0;
    if (t < SCAN_NB) g_bsum[t] = base + inc - v;
}
__global__ void k_scan_c() {
    int i = blockIdx.x * 256 + threadIdx.x;
    if (i < NN) {
        int o = g_off[i] + g_bsum[i >> 8];
        g_off[i] = o;
        g_pos[i] = o;
        g_dinv[i] = rsqrtf((float)g_deg[i]);
    }
    if (i == 0) g_off[NN] = NE;
}
__global__ void k_fill(const int* __restrict__ ei) {
    int e = blockIdx.x * 256 + threadIdx.x;
    if (e < NE) {
        int c = ei[NE + e];
        int p = atomicAdd(&g_pos[c], 1);
        g_src[p] = ei[e];
    }
}

// ---------------- aggregation: warp per node -> bf16 hi/lo feat planes ----------------
__device__ __forceinline__ void upd(float4& s, float4& mn, float4& mx, float d, float4 u) {
    u.x *= d; u.y *= d; u.z *= d; u.w *= d;
    s.x += u.x; s.y += u.y; s.z += u.z; s.w += u.w;
    mn.x = fminf(mn.x, u.x); mn.y = fminf(mn.y, u.y);
    mn.z = fminf(mn.z, u.z); mn.w = fminf(mn.w, u.w);
    mx.x = fmaxf(mx.x, u.x); mx.y = fmaxf(mx.y, u.y);
    mx.z = fmaxf(mx.z, u.z); mx.w = fmaxf(mx.w, u.w);
}
__device__ __forceinline__ void store_sec(int base, float4 v) {
    uint32_t h0, l0, h1, l1;
    split2(v.x, v.y, h0, l0);
    split2(v.z, v.w, h1, l1);
    *(uint2*)&g_feath[base] = make_uint2(h0, h1);
    *(uint2*)&g_featl[base] = make_uint2(l0, l1);
}
__global__ void __launch_bounds__(256) k_aggregate() {
    int w = threadIdx.x >> 5, lane = threadIdx.x & 31;
    int c = blockIdx.x * 8 + w;
    const float4* gv = (const float4*)g_gbuf;
    float dc = g_dinv[c];
    float4 hc = gv[c * 32 + lane];
    float4 v = make_float4(dc * hc.x, dc * hc.y, dc * hc.z, dc * hc.w);
    float4 s = v, mn = v, mx = v;
    int e0 = g_off[c], e1 = g_off[c + 1];
    int j = e0;
    for (; j + 4 <= e1; j += 4) {
        int r0 = __ldg(&g_src[j]);
        int r1 = __ldg(&g_src[j + 1]);
        int r2 = __ldg(&g_src[j + 2]);
        int r3 = __ldg(&g_src[j + 3]);
        float d0 = __ldg(&g_dinv[r0]);
        float d1 = __ldg(&g_dinv[r1]);
        float d2 = __ldg(&g_dinv[r2]);
        float d3 = __ldg(&g_dinv[r3]);
        float4 u0 = __ldg(&gv[r0 * 32 + lane]);
        float4 u1 = __ldg(&gv[r1 * 32 + lane]);
        float4 u2 = __ldg(&gv[r2 * 32 + lane]);
        float4 u3 = __ldg(&gv[r3 * 32 + lane]);
        upd(s, mn, mx, d0, u0);
        upd(s, mn, mx, d1, u1);
        upd(s, mn, mx, d2, u2);
        upd(s, mn, mx, d3, u3);
    }
    for (; j < e1; j++) {
        int r = __ldg(&g_src[j]);
        float d = __ldg(&g_dinv[r]);
        upd(s, mn, mx, d, __ldg(&gv[r * 32 + lane]));
    }
    float rdg = 1.0f / (float)g_deg[c];
    int b = c * 256 + lane * 2;
    float4 ad = make_float4(dc * s.x, dc * s.y, dc * s.z, dc * s.w);
    store_sec(b,       make_float4(ad.x * rdg, ad.y * rdg, ad.z * rdg, ad.w * rdg));
    store_sec(b + 64,  ad);
    store_sec(b + 128, make_float4(dc * mn.x, dc * mn.y, dc * mn.z, dc * mn.w));
    store_sec(b + 192, make_float4(dc * mx.x, dc * mx.y, dc * mx.z, dc * mx.w));
}

// ---------------- bf16 GEMM over concatenated planes, M=288 single-wave ----------------
// acc = Ah@Bh + Al@Bh + Ah@Bl expressed as one GEMM with K' = 3K:
//   segment 0: (Ah, Bh)   segment 1: (Al, Bh)   segment 2: (Ah, Bl)
// 288x128 CTA tile; 18 warps as 9x2 (32x64 each); grid 139 <= 148 SMs -> 1 wave.
// Static smem (39,936 B <= 48 KB) -> NO cudaFuncSetAttribute anywhere.
// EPI 0: fp32 -> g_gbuf ; EPI 2: relu(acc+bias) -> g_x1 hi/lo planes
#define SSTRW 12
#define OFF_B 13824u                  // A: 288*12 words = 13,824 B; B after
#define STG   19968u                  // stage bytes: A 13,824 + B 6,144

template <int K, int EPI, int ASRC, int BSRC>
__global__ void __launch_bounds__(576, 1) k_mma(const float* __restrict__ bias_p) {
    constexpr int KW = K / 2;         // u32 words per row per plane
    constexpr int KC16 = K / 16;      // chunks per segment (power of 2)
    constexpr int NC3 = 3 * KC16;     // total chunks
    const uint32_t* Agh = (ASRC == 0) ? g_xh : (ASRC == 1 ? g_feath : g_x1h);
    const uint32_t* Agl = (ASRC == 0) ? g_xl : (ASRC == 1 ? g_featl : g_x1l);
    const uint32_t* Bgh = (BSRC == 0) ? g_w0h : (BSRC == 1 ? g_c0h : (BSRC == 2 ? g_w1h : g_c1h));
    const uint32_t* Bgl = (BSRC == 0) ? g_w0l : (BSRC == 1 ? g_c0l : (BSRC == 2 ? g_w1l : g_c1l));

    __shared__ uint32_t Sm[2][STG / 4];

    const int tid = threadIdx.x;
    const int wid = tid >> 5, lane = tid & 31;
    const int g = lane >> 2, tig = lane & 3;
    const int wr = wid >> 1, wc = wid & 1;          // 9 warp-rows x 2 warp-cols
    const int m0 = blockIdx.x * MT;

    // loader geometry: A rows 0..287 (tid>>1), half = tid&1; B rows 0..127 (tid<256)
    const int arow_l = tid >> 1, ahalf = tid & 1;
    const bool okA = (m0 + arow_l) < NN;
    const int arow = okA ? (m0 + arow_l) : 0;
    const int szA = okA ? 16 : 0;
    const uint32_t aw4 = (uint32_t)(arow_l * SSTRW + ahalf * 4) * 4;
    const int brow = tid >> 1;
    const uint32_t bw4 = (uint32_t)(brow * SSTRW + ahalf * 4) * 4;

    const uint32_t sBase = smem_u32(&Sm[0][0]);

    // ldmatrix lane offsets
    const uint32_t aoff = (uint32_t)((wr * 32 + (lane & 15)) * SSTRW + (lane >> 4) * 4) * 4;
    const int mi = lane >> 3;
    const uint32_t boff = (uint32_t)((wc * 64 + ((mi >> 1) ? 8 : 0) + (lane & 7)) * SSTRW + (mi & 1) * 4) * 4;

    float acc[2][8][4];
    #pragma unroll
    for (int mt = 0; mt < 2; mt++)
        #pragma unroll
        for (int nt = 0; nt < 8; nt++)
            #pragma unroll
            for (int q = 0; q < 4; q++) acc[mt][nt][q] = 0.f;

#define ISSUE_CHUNK(chv, sv) do {                                         \
        const int _seg = (chv) / KC16;                                    \
        const int _inr = (chv) & (KC16 - 1);                              \
        const uint32_t* _Ap = (_seg == 1) ? Agl : Agh;                    \
        const uint32_t* _Bp = (_seg == 2) ? Bgl : Bgh;                    \
        const uint32_t _b = sBase + (uint32_t)(sv) * STG;                 \
        const size_t _ao = (size_t)arow * KW + _inr * 8 + ahalf * 4;      \
        CPA(_b + aw4, _Ap + _ao, szA);                                    \
        if (tid < 256) {                                                  \
            const size_t _bo = (size_t)brow * KW + _inr * 8 + ahalf * 4;  \
            CPA(_b + OFF_B + bw4, _Bp + _bo, 16);                         \
        }                                                                 \
        CPA_COMMIT();                                                     \
    } while (0)

    ISSUE_CHUNK(0, 0);
    ISSUE_CHUNK(1, 1);

    #pragma unroll 1
    for (int ch = 0; ch < NC3; ch++) {
        const int s = ch & 1;
        CPA_WAIT1();
        __syncthreads();
        const uint32_t sb = sBase + (uint32_t)s * STG;

        uint32_t a[2][4], bb[8][2];
        LDM4(a[0][0], a[0][1], a[0][2], a[0][3], sb + aoff);
        LDM4(a[1][0], a[1][1], a[1][2], a[1][3], sb + aoff + 768);
        LDM4(bb[0][0], bb[0][1], bb[1][0], bb[1][1], sb + OFF_B + boff);
        LDM4(bb[2][0], bb[2][1], bb[3][0], bb[3][1], sb + OFF_B + boff + 768);
        LDM4(bb[4][0], bb[4][1], bb[5][0], bb[5][1], sb + OFF_B + boff + 1536);
        LDM4(bb[6][0], bb[6][1], bb[7][0], bb[7][1], sb + OFF_B + boff + 2304);

        #pragma unroll
        for (int mt = 0; mt < 2; mt++)
            #pragma unroll
            for (int nt = 0; nt < 8; nt++) mma16(acc[mt][nt], a[mt], bb[nt]);

        __syncthreads();
        if (ch + 2 < NC3) {
            ISSUE_CHUNK(ch + 2, s);
        } else {
            CPA_COMMIT();   // keep group accounting balanced
        }
    }
#undef ISSUE_CHUNK

    // epilogue
    #pragma unroll
    for (int mt = 0; mt < 2; mt++) {
        const int r0 = m0 + wr * 32 + mt * 16 + g;
        const int r1 = r0 + 8;
        if (EPI == 0) {
            #pragma unroll
            for (int nt = 0; nt < 8; nt++) {
                const int col = wc * 64 + nt * 8 + tig * 2;
                if (r0 < NN)
                    *(float2*)&g_gbuf[(size_t)r0 * 128 + col] =
                        make_float2(acc[mt][nt][0], acc[mt][nt][1]);
                if (r1 < NN)
                    *(float2*)&g_gbuf[(size_t)r1 * 128 + col] =
                        make_float2(acc[mt][nt][2], acc[mt][nt][3]);
            }
        } else {
            #pragma unroll
            for (int nt = 0; nt < 8; nt++) {
                const int col = wc * 64 + nt * 8 + tig * 2;
                const float2 bv = *(const float2*)&bias_p[col];
                uint32_t h, l;
                if (r0 < NN) {
                    split2(fmaxf(acc[mt][nt][0] + bv.x, 0.f),
                           fmaxf(acc[mt][nt][1] + bv.y, 0.f), h, l);
                    g_x1h[r0 * 64 + (col >> 1)] = h;
                    g_x1l[r0 * 64 + (col >> 1)] = l;
                }
                if (r1 < NN) {
                    split2(fmaxf(acc[mt][nt][2] + bv.x, 0.f),
                           fmaxf(acc[mt][nt][3] + bv.y, 0.f), h, l);
                    g_x1h[r1 * 64 + (col >> 1)] = h;
                    g_x1l[r1 * 64 + (col >> 1)] = l;
                }
            }
        }
    }
}

// ---------------- classifier + log_softmax: warp per node (reads x1 planes) ----------------
__global__ void __launch_bounds__(256) k_out(const float* __restrict__ W,
                                             const float* __restrict__ bias,
                                             float* __restrict__ out) {
    __shared__ float ws[NCLS * 129];
    __shared__ float xs[8][128];
    __shared__ float bs[NCLS];
    int tid = threadIdx.x;
    for (int i = tid; i < NCLS * D; i += 256) {
        int c = i >> 7, k = i & 127;
        ws[c * 129 + k] = W[i];
    }
    if (tid < NCLS) bs[tid] = bias[tid];
    int w = tid >> 5, lane = tid & 31;
    int node = blockIdx.x * 8 + w;
    #pragma unroll
    for (int q = 0; q < 2; q++) {
        int idx = node * 64 + lane + 32 * q;
        uint32_t h = g_x1h[idx], l = g_x1l[idx];
        float v0 = __uint_as_float(h << 16) + __uint_as_float(l << 16);
        float v1 = __uint_as_float(h & 0xffff0000u) + __uint_as_float(l & 0xffff0000u);
        xs[w][2 * (lane + 32 * q)]     = v0;
        xs[w][2 * (lane + 32 * q) + 1] = v1;
    }
    __syncthreads();

    int c2 = 32 + (lane & 7);
    float acc0 = bs[lane];
    float acc1 = bs[c2];
    #pragma unroll 8
    for (int k = 0; k < D; k++) {
        float xv = xs[w][k];
        acc0 = fmaf(xv, ws[lane * 129 + k], acc0);
        acc1 = fmaf(xv, ws[c2 * 129 + k], acc1);
    }
    bool v1 = (lane < 8);
    float m = fmaxf(acc0, v1 ? acc1 : -1e30f);
    #pragma unroll
    for (int d = 16; d; d >>= 1) m = fmaxf(m, __shfl_xor_sync(0xffffffffu, m, d));
    float s = expf(acc0 - m) + (v1 ? expf(acc1 - m) : 0.f);
    #pragma unroll
    for (int d = 16; d; d >>= 1) s += __shfl_xor_sync(0xffffffffu, s, d);
    float lse = m + logf(s);
    out[node * NCLS + lane] = acc0 - lse;
    if (v1) out[node * NCLS + 32 + lane] = acc1 - lse;
}

// ---------------- launch ----------------
extern "C" void kernel_launch(void* const* d_in, const int* in_sizes, int n_in,
                              void* d_out, int out_size) {
    (void)in_sizes; (void)n_in; (void)out_size;
    const float* x    = (const float*)d_in[0];
    const int*   ei   = (const int*)d_in[1];
    const float* W0   = (const float*)d_in[2];
    const float* C0   = (const float*)d_in[3];
    const float* b0   = (const float*)d_in[4];
    const float* W1   = (const float*)d_in[5];
    const float* C1   = (const float*)d_in[6];
    const float* b1   = (const float*)d_in[7];
    const float* Wout = (const float*)d_in[8];
    const float* bout = (const float*)d_in[9];
    float* out = (float*)d_out;

    const int EB = (NE + 255) / 256;
    const int SXW = (NN * 64 + 128 * 64 + 255) / 256;

    k_init     <<<SCAN_NB, 256>>>();
    k_count    <<<EB, 256>>>(ei);
    k_split_xw0<<<SXW, 256>>>(x, W0);
    k_mma<128, 0, 0, 0><<<NT2, 576>>>(nullptr);   // h0 = x @ W0^T  [PROFILED]
    k_scan_a   <<<SCAN_NB, 256>>>();
    k_scan_b   <<<1, 256>>>();
    k_scan_c   <<<SCAN_NB, 256>>>();
    k_fill     <<<EB, 256>>>(ei);
    k_splitw<0><<<(128 * 256 + 255) / 256, 256>>>(C0, 128 * 256);
    k_splitw<1><<<(128 * 64 + 255) / 256, 256>>>(W1, 128 * 64);
    k_splitw<2><<<(128 * 256 + 255) / 256, 256>>>(C1, 128 * 256);

    // layer 0 aggregate + combine
    k_aggregate<<<NN / 8, 256>>>();
    k_mma<512, 2, 1, 1><<<NT2, 576>>>(b0);

    // layer 1
    k_mma<128, 0, 2, 2><<<NT2, 576>>>(nullptr);
    k_aggregate<<<NN / 8, 256>>>();
    k_mma<512, 2, 1, 3><<<NT2, 576>>>(b1);

    k_out<<<NN / 8, 256>>>(Wout, bout, out);
}

// round 15
// speedup vs baseline: 1.1134x; 1.1134x over previous
#include <cuda_runtime.h>
#include <math.h>
#include <stdint.h>

#define NN 40000
#define NE 640000
#define D 128
#define DC 512
#define NCLS 40
#define SCAN_NB ((NN + 255) / 256)   // 157
#define MT 288                        // GEMM M-tile (9 warp-rows x 32)
#define NT2 ((NN + MT - 1) / MT)      // 139 tiles -> single wave on 148 SMs

// ---------------- device scratch ----------------
__device__ int   g_deg[NN];
__device__ float g_dinv[NN];
__device__ int   g_off[NN + 1];
__device__ int   g_pos[NN];
__device__ int   g_src[NE];
__device__ int   g_bsum[SCAN_NB];
__device__ __align__(16) float g_gbuf[NN * D];        // lin output h (fp32, for gather)
// pre-split bf16 hi/lo planes (u32 = packed bf16x2 pair along k)
__device__ __align__(16) uint32_t g_xh[NN * 64],    g_xl[NN * 64];
__device__ __align__(16) uint32_t g_feath[NN * 256], g_featl[NN * 256];
__device__ __align__(16) uint32_t g_x1h[NN * 64],   g_x1l[NN * 64];
__device__ __align__(16) uint32_t g_w0h[128 * 64],  g_w0l[128 * 64];
__device__ __align__(16) uint32_t g_c0h[128 * 256], g_c0l[128 * 256];
__device__ __align__(16) uint32_t g_w1h[128 * 64],  g_w1l[128 * 64];
__device__ __align__(16) uint32_t g_c1h[128 * 256], g_c1l[128 * 256];

// ---------------- bf16 helpers ----------------
__device__ __forceinline__ void split2(float x0, float x1, uint32_t& hi2, uint32_t& lo2) {
    asm("cvt.rn.bf16x2.f32 %0, %1, %2;" : "=r"(hi2) : "f"(x1), "f"(x0));
    float h0 = __uint_as_float(hi2 << 16);
    float h1 = __uint_as_float(hi2 & 0xffff0000u);
    float l0 = x0 - h0, l1 = x1 - h1;
    asm("cvt.rn.bf16x2.f32 %0, %1, %2;" : "=r"(lo2) : "f"(l1), "f"(l0));
}
__device__ __forceinline__ void mma16(float* c, const uint32_t* a, const uint32_t* b) {
    asm volatile(
        "mma.sync.aligned.m16n8k16.row.col.f32.bf16.bf16.f32 "
        "{%0,%1,%2,%3}, {%4,%5,%6,%7}, {%8,%9}, {%0,%1,%2,%3};"
        : "+f"(c[0]), "+f"(c[1]), "+f"(c[2]), "+f"(c[3])
        : "r"(a[0]), "r"(a[1]), "r"(a[2]), "r"(a[3]), "r"(b[0]), "r"(b[1]));
}
__device__ __forceinline__ uint32_t smem_u32(const void* p) {
    uint32_t a;
    asm("{ .reg .u64 t; cvta.to.shared.u64 t, %1; cvt.u32.u64 %0, t; }" : "=r"(a) : "l"(p));
    return a;
}
#define LDM4(r0, r1, r2, r3, a) \
    asm volatile("ldmatrix.sync.aligned.m8n8.x4.shared.b16 {%0,%1,%2,%3}, [%4];" \
        : "=r"(r0), "=r"(r1), "=r"(r2), "=r"(r3) : "r"(a))
#define CPA(dst, src, sz) \
    asm volatile("cp.async.cg.shared.global [%0], [%1], 16, %2;" \
        :: "r"(dst), "l"(src), "r"(sz))
#define CPA_COMMIT() asm volatile("cp.async.commit_group;" ::: "memory")
#define CPA_WAIT1()  asm volatile("cp.async.wait_group 1;" ::: "memory")

// ---------------- small utilities ----------------
__device__ __forceinline__ int warp_iscan(int v) {
    #pragma unroll
    for (int d = 1; d < 32; d <<= 1) {
        int t = __shfl_up_sync(0xffffffffu, v, d);
        if ((threadIdx.x & 31) >= d) v += t;
    }
    return v;
}

// ---------------- pre-split kernels ----------------
__global__ void k_split_xw0(const float* __restrict__ x, const float* __restrict__ W0) {
    const int i = blockIdx.x * 256 + threadIdx.x;
    const int NW = 128 * 64;
    if (i < NW) {
        uint32_t h, l;
        split2(W0[2 * i], W0[2 * i + 1], h, l);
        g_w0h[i] = h; g_w0l[i] = l;
    }
    const int j = i - NW;
    if (j >= 0 && j < NN * 64) {
        uint32_t h, l;
        split2(x[2 * j], x[2 * j + 1], h, l);
        g_xh[j] = h; g_xl[j] = l;
    }
}
// DST: 0 = C0, 1 = W1, 2 = C1
template <int DST>
__global__ void k_splitw(const float* __restrict__ src, int npairs) {
    const int i = blockIdx.x * 256 + threadIdx.x;
    if (i >= npairs) return;
    uint32_t h, l;
    split2(src[2 * i], src[2 * i + 1], h, l);
    if (DST == 0) { g_c0h[i] = h; g_c0l[i] = l; }
    if (DST == 1) { g_w1h[i] = h; g_w1l[i] = l; }
    if (DST == 2) { g_c1h[i] = h; g_c1l[i] = l; }
}

// ---------------- graph preprocessing ----------------
__global__ void k_init() {
    int i = blockIdx.x * 256 + threadIdx.x;
    if (i < NN) g_deg[i] = 1;
}
__global__ void k_count(const int* __restrict__ ei) {
    int e = blockIdx.x * 256 + threadIdx.x;
    if (e < NE) atomicAdd(&g_deg[ei[NE + e]], 1);
}
__global__ void k_scan_a() {
    __shared__ int wsum[8];
    int i = blockIdx.x * 256 + threadIdx.x;
    int cnt = (i < NN) ? (g_deg[i] - 1) : 0;
    int inc = warp_iscan(cnt);
    int wid = threadIdx.x >> 5, lane = threadIdx.x & 31;
    if (lane == 31) wsum[wid] = inc;
    __syncthreads();
    if (wid == 0) {
        int v = (lane < 8) ? wsum[lane] : 0;
        v = warp_iscan(v);
        if (lane < 8) wsum[lane] = v;
    }
    __syncthreads();
    int base = wid ? wsum[wid - 1] : 0;
    if (i < NN) g_off[i] = base + inc - cnt;
    if (threadIdx.x == 255) g_bsum[blockIdx.x] = base + inc;
}
__global__ void k_scan_b() {
    __shared__ int wsum[8];
    int t = threadIdx.x;
    int v = (t < SCAN_NB) ? g_bsum[t] : 0;
    int inc = warp_iscan(v);
    int wid = t >> 5, lane = t & 31;
    if (lane == 31) wsum[wid] = inc;
    __syncthreads();
    if (wid == 0) {
        int u = (lane < 8) ? wsum[lane] : 0;
        u = warp_iscan(u);
        if (lane < 8) wsum[lane] = u;
    }
    __syncthreads();
    int base = wid ? wsum[wid - 1] : 0;
    if (t < SCAN_NB) g_bsum[t] = base + inc - v;
}
__global__ void k_scan_c() {
    int i = blockIdx.x * 256 + threadIdx.x;
    if (i < NN) {
        int o = g_off[i] + g_bsum[i >> 8];
        g_off[i] = o;
        g_pos[i] = o;
        g_dinv[i] = rsqrtf((float)g_deg[i]);
    }
    if (i == 0) g_off[NN] = NE;
}
__global__ void k_fill(const int* __restrict__ ei) {
    int e = blockIdx.x * 256 + threadIdx.x;
    if (e < NE) {
        int c = ei[NE + e];
        int p = atomicAdd(&g_pos[c], 1);
        g_src[p] = ei[e];
    }
}

// ---------------- aggregation: warp per node -> bf16 hi/lo feat planes ----------------
__device__ __forceinline__ void upd(float4& s, float4& mn, float4& mx, float d, float4 u) {
    u.x *= d; u.y *= d; u.z *= d; u.w *= d;
    s.x += u.x; s.y += u.y; s.z += u.z; s.w += u.w;
    mn.x = fminf(mn.x, u.x); mn.y = fminf(mn.y, u.y);
    mn.z = fminf(mn.z, u.z); mn.w = fminf(mn.w, u.w);
    mx.x = fmaxf(mx.x, u.x); mx.y = fmaxf(mx.y, u.y);
    mx.z = fmaxf(mx.z, u.z); mx.w = fmaxf(mx.w, u.w);
}
__device__ __forceinline__ void store_sec(int base, float4 v) {
    uint32_t h0, l0, h1, l1;
    split2(v.x, v.y, h0, l0);
    split2(v.z, v.w, h1, l1);
    *(uint2*)&g_feath[base] = make_uint2(h0, h1);
    *(uint2*)&g_featl[base] = make_uint2(l0, l1);
}
__global__ void __launch_bounds__(256) k_aggregate() {
    int w = threadIdx.x >> 5, lane = threadIdx.x & 31;
    int c = blockIdx.x * 8 + w;
    const float4* gv = (const float4*)g_gbuf;
    float dc = g_dinv[c];
    float4 hc = gv[c * 32 + lane];
    float4 v = make_float4(dc * hc.x, dc * hc.y, dc * hc.z, dc * hc.w);
    float4 s = v, mn = v, mx = v;
    int e0 = g_off[c], e1 = g_off[c + 1];
    int j = e0;
    for (; j + 4 <= e1; j += 4) {
        int r0 = __ldg(&g_src[j]);
        int r1 = __ldg(&g_src[j + 1]);
        int r2 = __ldg(&g_src[j + 2]);
        int r3 = __ldg(&g_src[j + 3]);
        float d0 = __ldg(&g_dinv[r0]);
        float d1 = __ldg(&g_dinv[r1]);
        float d2 = __ldg(&g_dinv[r2]);
        float d3 = __ldg(&g_dinv[r3]);
        float4 u0 = __ldg(&gv[r0 * 32 + lane]);
        float4 u1 = __ldg(&gv[r1 * 32 + lane]);
        float4 u2 = __ldg(&gv[r2 * 32 + lane]);
        float4 u3 = __ldg(&gv[r3 * 32 + lane]);
        upd(s, mn, mx, d0, u0);
        upd(s, mn, mx, d1, u1);
        upd(s, mn, mx, d2, u2);
        upd(s, mn, mx, d3, u3);
    }
    for (; j < e1; j++) {
        int r = __ldg(&g_src[j]);
        float d = __ldg(&g_dinv[r]);
        upd(s, mn, mx, d, __ldg(&gv[r * 32 + lane]));
    }
    float rdg = 1.0f / (float)g_deg[c];
    int b = c * 256 + lane * 2;
    float4 ad = make_float4(dc * s.x, dc * s.y, dc * s.z, dc * s.w);
    store_sec(b,       make_float4(ad.x * rdg, ad.y * rdg, ad.z * rdg, ad.w * rdg));
    store_sec(b + 64,  ad);
    store_sec(b + 128, make_float4(dc * mn.x, dc * mn.y, dc * mn.z, dc * mn.w));
    store_sec(b + 192, make_float4(dc * mx.x, dc * mx.y, dc * mx.z, dc * mx.w));
}

// ---------------- bf16 GEMM: concatenated planes, M=288, 3-stage, 1 bar/chunk ----------
// acc = Ah@Bh + Al@Bh + Ah@Bl as one GEMM with K' = 3K (segments).
// Tight smem: row = 8 words (32 B), 16B-chunk swizzle c ^= (row>>2)&1 -> conflict-free
// for cp.async writes and all ldmatrix phases (row offsets are multiples of 8).
// Stage = A(288*8) + B(128*8) words = 13,312 B; 3 stages = 39,936 B static.
// Mainloop: wait_group 1 -> ONE __syncthreads -> issue chunk+2 -> ldmatrix+16 MMA.
// EPI 0: fp32 -> g_gbuf ; EPI 2: relu(acc+bias) -> g_x1 hi/lo planes
#define OFF_B 9216u
#define STG   13312u

template <int K, int EPI, int ASRC, int BSRC>
__global__ void __launch_bounds__(576, 1) k_mma(const float* __restrict__ bias_p) {
    constexpr int KW = K / 2;         // u32 words per row per plane
    constexpr int KC16 = K / 16;      // chunks per segment (power of 2)
    constexpr int NC3 = 3 * KC16;     // total chunks
    const uint32_t* Agh = (ASRC == 0) ? g_xh : (ASRC == 1 ? g_feath : g_x1h);
    const uint32_t* Agl = (ASRC == 0) ? g_xl : (ASRC == 1 ? g_featl : g_x1l);
    const uint32_t* Bgh = (BSRC == 0) ? g_w0h : (BSRC == 1 ? g_c0h : (BSRC == 2 ? g_w1h : g_c1h));
    const uint32_t* Bgl = (BSRC == 0) ? g_w0l : (BSRC == 1 ? g_c0l : (BSRC == 2 ? g_w1l : g_c1l));

    __shared__ uint32_t Sm[3][STG / 4];

    const int tid = threadIdx.x;
    const int wid = tid >> 5, lane = tid & 31;
    const int g = lane >> 2, tig = lane & 3;
    const int wr = wid >> 1, wc = wid & 1;          // 9 warp-rows x 2 warp-cols
    const int m0 = blockIdx.x * MT;

    // loader geometry: A rows 0..287 (tid>>1), half = tid&1; B rows 0..127 (tid<256)
    const int arow_l = tid >> 1, ahalf = tid & 1;
    const bool okA = (m0 + arow_l) < NN;
    const int arow = okA ? (m0 + arow_l) : 0;
    const int szA = okA ? 16 : 0;
    // swizzled store chunk: half ^ bit2(row)
    const uint32_t aw4 = (uint32_t)(arow_l * 8 + (ahalf ^ ((arow_l >> 2) & 1)) * 4) * 4;
    const int brow = tid >> 1;
    const uint32_t bw4 = (uint32_t)(brow * 8 + (ahalf ^ ((brow >> 2) & 1)) * 4) * 4;

    const uint32_t sBase = smem_u32(&Sm[0][0]);

    // ldmatrix lane offsets (swizzle bit = (lane>>2)&1 for both A and B)
    const int swb = (lane >> 2) & 1;
    const uint32_t aoff = (uint32_t)((wr * 32 + (lane & 15)) * 8 + ((lane >> 4) ^ swb) * 4) * 4;
    const int mi = lane >> 3;
    const uint32_t boff = (uint32_t)((wc * 64 + ((mi >> 1) ? 8 : 0) + (lane & 7)) * 8
                                     + ((mi & 1) ^ swb) * 4) * 4;

    float acc[2][8][4];
    #pragma unroll
    for (int mt = 0; mt < 2; mt++)
        #pragma unroll
        for (int nt = 0; nt < 8; nt++)
            #pragma unroll
            for (int q = 0; q < 4; q++) acc[mt][nt][q] = 0.f;

#define ISSUE_CHUNK(chv, sv) do {                                         \
        const int _seg = (chv) / KC16;                                    \
        const int _inr = (chv) & (KC16 - 1);                              \
        const uint32_t* _Ap = (_seg == 1) ? Agl : Agh;                    \
        const uint32_t* _Bp = (_seg == 2) ? Bgl : Bgh;                    \
        const uint32_t _b = sBase + (uint32_t)(sv) * STG;                 \
        const size_t _ao = (size_t)arow * KW + _inr * 8 + ahalf * 4;      \
        CPA(_b + aw4, _Ap + _ao, szA);                                    \
        if (tid < 256) {                                                  \
            const size_t _bo = (size_t)brow * KW + _inr * 8 + ahalf * 4;  \
            CPA(_b + OFF_B + bw4, _Bp + _bo, 16);                         \
        }                                                                 \
        CPA_COMMIT();                                                     \
    } while (0)

    ISSUE_CHUNK(0, 0);
    ISSUE_CHUNK(1, 1);

    int s = 0;
    #pragma unroll 1
    for (int ch = 0; ch < NC3; ch++) {
        CPA_WAIT1();
        __syncthreads();
        // issue chunk ch+2 into the stage consumed at chunk ch-1 (safe: barrier above
        // orders all warps' chunk ch-1 ldmatrix reads before these writes)
        if (ch + 2 < NC3) {
            int s2 = s + 2; if (s2 >= 3) s2 -= 3;
            ISSUE_CHUNK(ch + 2, s2);
        }
        const uint32_t sb = sBase + (uint32_t)s * STG;

        uint32_t a[2][4], bb[8][2];
        LDM4(a[0][0], a[0][1], a[0][2], a[0][3], sb + aoff);
        LDM4(a[1][0], a[1][1], a[1][2], a[1][3], sb + aoff + 512);
        LDM4(bb[0][0], bb[0][1], bb[1][0], bb[1][1], sb + OFF_B + boff);
        LDM4(bb[2][0], bb[2][1], bb[3][0], bb[3][1], sb + OFF_B + boff + 512);
        LDM4(bb[4][0], bb[4][1], bb[5][0], bb[5][1], sb + OFF_B + boff + 1024);
        LDM4(bb[6][0], bb[6][1], bb[7][0], bb[7][1], sb + OFF_B + boff + 1536);

        #pragma unroll
        for (int mt = 0; mt < 2; mt++)
            #pragma unroll
            for (int nt = 0; nt < 8; nt++) mma16(acc[mt][nt], a[mt], bb[nt]);

        s = (s == 2) ? 0 : s + 1;
    }
#undef ISSUE_CHUNK

    // epilogue
    #pragma unroll
    for (int mt = 0; mt < 2; mt++) {
        const int r0 = m0 + wr * 32 + mt * 16 + g;
        const int r1 = r0 + 8;
        if (EPI == 0) {
            #pragma unroll
            for (int nt = 0; nt < 8; nt++) {
                const int col = wc * 64 + nt * 8 + tig * 2;
                if (r0 < NN)
                    *(float2*)&g_gbuf[(size_t)r0 * 128 + col] =
                        make_float2(acc[mt][nt][0], acc[mt][nt][1]);
                if (r1 < NN)
                    *(float2*)&g_gbuf[(size_t)r1 * 128 + col] =
                        make_float2(acc[mt][nt][2], acc[mt][nt][3]);
            }
        } else {
            #pragma unroll
            for (int nt = 0; nt < 8; nt++) {
                const int col = wc * 64 + nt * 8 + tig * 2;
                const float2 bv = *(const float2*)&bias_p[col];
                uint32_t h, l;
                if (r0 < NN) {
                    split2(fmaxf(acc[mt][nt][0] + bv.x, 0.f),
                           fmaxf(acc[mt][nt][1] + bv.y, 0.f), h, l);
                    g_x1h[r0 * 64 + (col >> 1)] = h;
                    g_x1l[r0 * 64 + (col >> 1)] = l;
                }
                if (r1 < NN) {
                    split2(fmaxf(acc[mt][nt][2] + bv.x, 0.f),
                           fmaxf(acc[mt][nt][3] + bv.y, 0.f), h, l);
                    g_x1h[r1 * 64 + (col >> 1)] = h;
                    g_x1l[r1 * 64 + (col >> 1)] = l;
                }
            }
        }
    }
}

// ---------------- classifier + log_softmax: warp per node (reads x1 planes) ----------------
__global__ void __launch_bounds__(256) k_out(const float* __restrict__ W,
                                             const float* __restrict__ bias,
                                             float* __restrict__ out) {
    __shared__ float ws[NCLS * 129];
    __shared__ float xs[8][128];
    __shared__ float bs[NCLS];
    int tid = threadIdx.x;
    for (int i = tid; i < NCLS * D; i += 256) {
        int c = i >> 7, k = i & 127;
        ws[c * 129 + k] = W[i];
    }
    if (tid < NCLS) bs[tid] = bias[tid];
    int w = tid >> 5, lane = tid & 31;
    int node = blockIdx.x * 8 + w;
    #pragma unroll
    for (int q = 0; q < 2; q++) {
        int idx = node * 64 + lane + 32 * q;
        uint32_t h = g_x1h[idx], l = g_x1l[idx];
        float v0 = __uint_as_float(h << 16) + __uint_as_float(l << 16);
        float v1 = __uint_as_float(h & 0xffff0000u) + __uint_as_float(l & 0xffff0000u);
        xs[w][2 * (lane + 32 * q)]     = v0;
        xs[w][2 * (lane + 32 * q) + 1] = v1;
    }
    __syncthreads();

    int c2 = 32 + (lane & 7);
    float acc0 = bs[lane];
    float acc1 = bs[c2];
    #pragma unroll 8
    for (int k = 0; k < D; k++) {
        float xv = xs[w][k];
        acc0 = fmaf(xv, ws[lane * 129 + k], acc0);
        acc1 = fmaf(xv, ws[c2 * 129 + k], acc1);
    }
    bool v1 = (lane < 8);
    float m = fmaxf(acc0, v1 ? acc1 : -1e30f);
    #pragma unroll
    for (int d = 16; d; d >>= 1) m = fmaxf(m, __shfl_xor_sync(0xffffffffu, m, d));
    float s = expf(acc0 - m) + (v1 ? expf(acc1 - m) : 0.f);
    #pragma unroll
    for (int d = 16; d; d >>= 1) s += __shfl_xor_sync(0xffffffffu, s, d);
    float lse = m + logf(s);
    out[node * NCLS + lane] = acc0 - lse;
    if (v1) out[node * NCLS + 32 + lane] = acc1 - lse;
}

// ---------------- launch ----------------
extern "C" void kernel_launch(void* const* d_in, const int* in_sizes, int n_in,
                              void* d_out, int out_size) {
    (void)in_sizes; (void)n_in; (void)out_size;
    const float* x    = (const float*)d_in[0];
    const int*   ei   = (const int*)d_in[1];
    const float* W0   = (const float*)d_in[2];
    const float* C0   = (const float*)d_in[3];
    const float* b0   = (const float*)d_in[4];
    const float* W1   = (const float*)d_in[5];
    const float* C1   = (const float*)d_in[6];
    const float* b1   = (const float*)d_in[7];
    const float* Wout = (const float*)d_in[8];
    const float* bout = (const float*)d_in[9];
    float* out = (float*)d_out;

    const int EB = (NE + 255) / 256;
    const int SXW = (NN * 64 + 128 * 64 + 255) / 256;

    k_init     <<<SCAN_NB, 256>>>();
    k_count    <<<EB, 256>>>(ei);
    k_split_xw0<<<SXW, 256>>>(x, W0);
    k_mma<128, 0, 0, 0><<<NT2, 576>>>(nullptr);   // h0 = x @ W0^T  [PROFILED]
    k_scan_a   <<<SCAN_NB, 256>>>();
    k_scan_b   <<<1, 256>>>();
    k_scan_c   <<<SCAN_NB, 256>>>();
    k_fill     <<<EB, 256>>>(ei);
    k_splitw<0><<<(128 * 256 + 255) / 256, 256>>>(C0, 128 * 256);
    k_splitw<1><<<(128 * 64 + 255) / 256, 256>>>(W1, 128 * 64);
    k_splitw<2><<<(128 * 256 + 255) / 256, 256>>>(C1, 128 * 256);

    // layer 0 aggregate + combine
    k_aggregate<<<NN / 8, 256>>>();
    k_mma<512, 2, 1, 1><<<NT2, 576>>>(b0);

    // layer 1
    k_mma<128, 0, 2, 2><<<NT2, 576>>>(nullptr);
    k_aggregate<<<NN / 8, 256>>>();
    k_mma<512, 2, 1, 3><<<NT2, 576>>>(b1);

    k_out<<<NN / 8, 256>>>(Wout, bout, out);
}

// round 16
// speedup vs baseline: 1.1229x; 1.0086x over previous
#include <cuda_runtime.h>
#include <math.h>
#include <stdint.h>

#define NN 40000
#define NE 640000
#define D 128
#define DC 512
#define NCLS 40
#define SCAN_NB ((NN + 255) / 256)   // 157
#define MT 320                        // GEMM M-tile (10 warp-rows x 32)
#define NT2 ((NN + MT - 1) / MT)      // 125 tiles -> single wave on 148 SMs

// ---------------- device scratch ----------------
__device__ int   g_deg[NN];
__device__ float g_dinv[NN];
__device__ int   g_off[NN + 1];
__device__ int   g_pos[NN];
__device__ int   g_src[NE];
__device__ int   g_bsum[SCAN_NB];
__device__ __align__(16) float g_gbuf[NN * D];        // lin output h (fp32, for gather)
// pre-split bf16 hi/lo planes (u32 = packed bf16x2 pair along k)
__device__ __align__(16) uint32_t g_xh[NN * 64],    g_xl[NN * 64];
__device__ __align__(16) uint32_t g_feath[NN * 256], g_featl[NN * 256];
__device__ __align__(16) uint32_t g_x1h[NN * 64],   g_x1l[NN * 64];
__device__ __align__(16) uint32_t g_w0h[128 * 64],  g_w0l[128 * 64];
__device__ __align__(16) uint32_t g_c0h[128 * 256], g_c0l[128 * 256];
__device__ __align__(16) uint32_t g_w1h[128 * 64],  g_w1l[128 * 64];
__device__ __align__(16) uint32_t g_c1h[128 * 256], g_c1l[128 * 256];

// ---------------- bf16 helpers ----------------
__device__ __forceinline__ void split2(float x0, float x1, uint32_t& hi2, uint32_t& lo2) {
    asm("cvt.rn.bf16x2.f32 %0, %1, %2;" : "=r"(hi2) : "f"(x1), "f"(x0));
    float h0 = __uint_as_float(hi2 << 16);
    float h1 = __uint_as_float(hi2 & 0xffff0000u);
    float l0 = x0 - h0, l1 = x1 - h1;
    asm("cvt.rn.bf16x2.f32 %0, %1, %2;" : "=r"(lo2) : "f"(l1), "f"(l0));
}
__device__ __forceinline__ void mma16(float* c, const uint32_t* a, const uint32_t* b) {
    asm volatile(
        "mma.sync.aligned.m16n8k16.row.col.f32.bf16.bf16.f32 "
        "{%0,%1,%2,%3}, {%4,%5,%6,%7}, {%8,%9}, {%0,%1,%2,%3};"
        : "+f"(c[0]), "+f"(c[1]), "+f"(c[2]), "+f"(c[3])
        : "r"(a[0]), "r"(a[1]), "r"(a[2]), "r"(a[3]), "r"(b[0]), "r"(b[1]));
}
__device__ __forceinline__ uint32_t smem_u32(const void* p) {
    uint32_t a;
    asm("{ .reg .u64 t; cvta.to.shared.u64 t, %1; cvt.u32.u64 %0, t; }" : "=r"(a) : "l"(p));
    return a;
}
#define LDM4(r0, r1, r2, r3, a) \
    asm volatile("ldmatrix.sync.aligned.m8n8.x4.shared.b16 {%0,%1,%2,%3}, [%4];" \
        : "=r"(r0), "=r"(r1), "=r"(r2), "=r"(r3) : "r"(a))
#define CPA(dst, src, sz) \
    asm volatile("cp.async.cg.shared.global [%0], [%1], 16, %2;" \
        :: "r"(dst), "l"(src), "r"(sz))
#define CPA_COMMIT() asm volatile("cp.async.commit_group;" ::: "memory")
#define CPA_WAIT1()  asm volatile("cp.async.wait_group 1;" ::: "memory")

// ---------------- small utilities ----------------
__device__ __forceinline__ int warp_iscan(int v) {
    #pragma unroll
    for (int d = 1; d < 32; d <<= 1) {
        int t = __shfl_up_sync(0xffffffffu, v, d);
        if ((threadIdx.x & 31) >= d) v += t;
    }
    return v;
}

// ---------------- pre-split kernels ----------------
__global__ void k_split_xw0(const float* __restrict__ x, const float* __restrict__ W0) {
    const int i = blockIdx.x * 256 + threadIdx.x;
    const int NW = 128 * 64;
    if (i < NW) {
        uint32_t h, l;
        split2(W0[2 * i], W0[2 * i + 1], h, l);
        g_w0h[i] = h; g_w0l[i] = l;
    }
    const int j = i - NW;
    if (j >= 0 && j < NN * 64) {
        uint32_t h, l;
        split2(x[2 * j], x[2 * j + 1], h, l);
        g_xh[j] = h; g_xl[j] = l;
    }
}
// DST: 0 = C0, 1 = W1, 2 = C1
template <int DST>
__global__ void k_splitw(const float* __restrict__ src, int npairs) {
    const int i = blockIdx.x * 256 + threadIdx.x;
    if (i >= npairs) return;
    uint32_t h, l;
    split2(src[2 * i], src[2 * i + 1], h, l);
    if (DST == 0) { g_c0h[i] = h; g_c0l[i] = l; }
    if (DST == 1) { g_w1h[i] = h; g_w1l[i] = l; }
    if (DST == 2) { g_c1h[i] = h; g_c1l[i] = l; }
}

// ---------------- graph preprocessing ----------------
__global__ void k_init() {
    int i = blockIdx.x * 256 + threadIdx.x;
    if (i < NN) g_deg[i] = 1;
}
__global__ void k_count(const int* __restrict__ ei) {
    int e = blockIdx.x * 256 + threadIdx.x;
    if (e < NE) atomicAdd(&g_deg[ei[NE + e]], 1);
}
__global__ void k_scan_a() {
    __shared__ int wsum[8];
    int i = blockIdx.x * 256 + threadIdx.x;
    int cnt = (i < NN) ? (g_deg[i] - 1) : 0;
    int inc = warp_iscan(cnt);
    int wid = threadIdx.x >> 5, lane = threadIdx.x & 31;
    if (lane == 31) wsum[wid] = inc;
    __syncthreads();
    if (wid == 0) {
        int v = (lane < 8) ? wsum[lane] : 0;
        v = warp_iscan(v);
        if (lane < 8) wsum[lane] = v;
    }
    __syncthreads();
    int base = wid ? wsum[wid - 1] : 0;
    if (i < NN) g_off[i] = base + inc - cnt;
    if (threadIdx.x == 255) g_bsum[blockIdx.x] = base + inc;
}
__global__ void k_scan_b() {
    __shared__ int wsum[8];
    int t = threadIdx.x;
    int v = (t < SCAN_NB) ? g_bsum[t] : 0;
    int inc = warp_iscan(v);
    int wid = t >> 5, lane = t & 31;
    if (lane == 31) wsum[wid] = inc;
    __syncthreads();
    if (wid == 0) {
        int u = (lane < 8) ? wsum[lane] : 0;
        u = warp_iscan(u);
        if (lane < 8) wsum[lane] = u;
    }
    __syncthreads();
    int base = wid ? wsum[wid - 1] : 0;
    if (t < SCAN_NB) g_bsum[t] = base + inc - v;
}
__global__ void k_scan_c() {
    int i = blockIdx.x * 256 + threadIdx.x;
    if (i < NN) {
        int o = g_off[i] + g_bsum[i >> 8];
        g_off[i] = o;
        g_pos[i] = o;
        g_dinv[i] = rsqrtf((float)g_deg[i]);
    }
    if (i == 0) g_off[NN] = NE;
}
__global__ void k_fill(const int* __restrict__ ei) {
    int e = blockIdx.x * 256 + threadIdx.x;
    if (e < NE) {
        int c = ei[NE + e];
        int p = atomicAdd(&g_pos[c], 1);
        g_src[p] = ei[e];
    }
}

// ---------------- aggregation: warp per node -> bf16 hi/lo feat planes ----------------
__device__ __forceinline__ void upd(float4& s, float4& mn, float4& mx, float d, float4 u) {
    u.x *= d; u.y *= d; u.z *= d; u.w *= d;
    s.x += u.x; s.y += u.y; s.z += u.z; s.w += u.w;
    mn.x = fminf(mn.x, u.x); mn.y = fminf(mn.y, u.y);
    mn.z = fminf(mn.z, u.z); mn.w = fminf(mn.w, u.w);
    mx.x = fmaxf(mx.x, u.x); mx.y = fmaxf(mx.y, u.y);
    mx.z = fmaxf(mx.z, u.z); mx.w = fmaxf(mx.w, u.w);
}
__device__ __forceinline__ void store_sec(int base, float4 v) {
    uint32_t h0, l0, h1, l1;
    split2(v.x, v.y, h0, l0);
    split2(v.z, v.w, h1, l1);
    *(uint2*)&g_feath[base] = make_uint2(h0, h1);
    *(uint2*)&g_featl[base] = make_uint2(l0, l1);
}
__global__ void __launch_bounds__(256) k_aggregate() {
    int w = threadIdx.x >> 5, lane = threadIdx.x & 31;
    int c = blockIdx.x * 8 + w;
    const float4* gv = (const float4*)g_gbuf;
    float dc = g_dinv[c];
    float4 hc = gv[c * 32 + lane];
    float4 v = make_float4(dc * hc.x, dc * hc.y, dc * hc.z, dc * hc.w);
    float4 s = v, mn = v, mx = v;
    int e0 = g_off[c], e1 = g_off[c + 1];
    int j = e0;
    for (; j + 4 <= e1; j += 4) {
        int r0 = __ldg(&g_src[j]);
        int r1 = __ldg(&g_src[j + 1]);
        int r2 = __ldg(&g_src[j + 2]);
        int r3 = __ldg(&g_src[j + 3]);
        float d0 = __ldg(&g_dinv[r0]);
        float d1 = __ldg(&g_dinv[r1]);
        float d2 = __ldg(&g_dinv[r2]);
        float d3 = __ldg(&g_dinv[r3]);
        float4 u0 = __ldg(&gv[r0 * 32 + lane]);
        float4 u1 = __ldg(&gv[r1 * 32 + lane]);
        float4 u2 = __ldg(&gv[r2 * 32 + lane]);
        float4 u3 = __ldg(&gv[r3 * 32 + lane]);
        upd(s, mn, mx, d0, u0);
        upd(s, mn, mx, d1, u1);
        upd(s, mn, mx, d2, u2);
        upd(s, mn, mx, d3, u3);
    }
    for (; j < e1; j++) {
        int r = __ldg(&g_src[j]);
        float d = __ldg(&g_dinv[r]);
        upd(s, mn, mx, d, __ldg(&gv[r * 32 + lane]));
    }
    float rdg = 1.0f / (float)g_deg[c];
    int b = c * 256 + lane * 2;
    float4 ad = make_float4(dc * s.x, dc * s.y, dc * s.z, dc * s.w);
    store_sec(b,       make_float4(ad.x * rdg, ad.y * rdg, ad.z * rdg, ad.w * rdg));
    store_sec(b + 64,  ad);
    store_sec(b + 128, make_float4(dc * mn.x, dc * mn.y, dc * mn.z, dc * mn.w));
    store_sec(b + 192, make_float4(dc * mx.x, dc * mx.y, dc * mx.z, dc * mx.w));
}

// ---------------- bf16 GEMM: concatenated planes, M=320, 3-stage, 1 bar/chunk ----------
// acc = Ah@Bh + Al@Bh + Ah@Bl as one GEMM with K' = 3K (segments).
// 640 threads = 20 warps -> exactly 5 warps per SMSP (balanced schedulers).
// Tight smem: row = 8 words (32 B), 16B-chunk swizzle c ^= (row>>2)&1.
// Stage = A(320*8) + B(128*8) words = 14,336 B; 3 stages = 43,008 B static.
// Mainloop: wait_group 1 -> ONE __syncthreads -> issue chunk+2 -> ldmatrix+16 MMA.
// EPI 0: fp32 -> g_gbuf ; EPI 2: relu(acc+bias) -> g_x1 hi/lo planes
#define OFF_B 10240u
#define STG   14336u

template <int K, int EPI, int ASRC, int BSRC>
__global__ void __launch_bounds__(640, 1) k_mma(const float* __restrict__ bias_p) {
    constexpr int KW = K / 2;         // u32 words per row per plane
    constexpr int KC16 = K / 16;      // chunks per segment (power of 2)
    constexpr int NC3 = 3 * KC16;     // total chunks
    const uint32_t* Agh = (ASRC == 0) ? g_xh : (ASRC == 1 ? g_feath : g_x1h);
    const uint32_t* Agl = (ASRC == 0) ? g_xl : (ASRC == 1 ? g_featl : g_x1l);
    const uint32_t* Bgh = (BSRC == 0) ? g_w0h : (BSRC == 1 ? g_c0h : (BSRC == 2 ? g_w1h : g_c1h));
    const uint32_t* Bgl = (BSRC == 0) ? g_w0l : (BSRC == 1 ? g_c0l : (BSRC == 2 ? g_w1l : g_c1l));

    __shared__ uint32_t Sm[3][STG / 4];

    const int tid = threadIdx.x;
    const int wid = tid >> 5, lane = tid & 31;
    const int g = lane >> 2, tig = lane & 3;
    const int wr = wid >> 1, wc = wid & 1;          // 10 warp-rows x 2 warp-cols
    const int m0 = blockIdx.x * MT;

    // loader geometry: A rows 0..319 (tid>>1), half = tid&1; B rows 0..127 (tid<256)
    const int arow_l = tid >> 1, ahalf = tid & 1;
    const bool okA = (m0 + arow_l) < NN;
    const int arow = okA ? (m0 + arow_l) : 0;
    const int szA = okA ? 16 : 0;
    // swizzled store chunk: half ^ bit2(row)
    const uint32_t aw4 = (uint32_t)(arow_l * 8 + (ahalf ^ ((arow_l >> 2) & 1)) * 4) * 4;
    const int brow = tid >> 1;
    const uint32_t bw4 = (uint32_t)(brow * 8 + (ahalf ^ ((brow >> 2) & 1)) * 4) * 4;

    const uint32_t sBase = smem_u32(&Sm[0][0]);

    // ldmatrix lane offsets (swizzle bit = (lane>>2)&1 for both A and B)
    const int swb = (lane >> 2) & 1;
    const uint32_t aoff = (uint32_t)((wr * 32 + (lane & 15)) * 8 + ((lane >> 4) ^ swb) * 4) * 4;
    const int mi = lane >> 3;
    const uint32_t boff = (uint32_t)((wc * 64 + ((mi >> 1) ? 8 : 0) + (lane & 7)) * 8
                                     + ((mi & 1) ^ swb) * 4) * 4;

    float acc[2][8][4];
    #pragma unroll
    for (int mt = 0; mt < 2; mt++)
        #pragma unroll
        for (int nt = 0; nt < 8; nt++)
            #pragma unroll
            for (int q = 0; q < 4; q++) acc[mt][nt][q] = 0.f;

#define ISSUE_CHUNK(chv, sv) do {                                         \
        const int _seg = (chv) / KC16;                                    \
        const int _inr = (chv) & (KC16 - 1);                              \
        const uint32_t* _Ap = (_seg == 1) ? Agl : Agh;                    \
        const uint32_t* _Bp = (_seg == 2) ? Bgl : Bgh;                    \
        const uint32_t _b = sBase + (uint32_t)(sv) * STG;                 \
        const size_t _ao = (size_t)arow * KW + _inr * 8 + ahalf * 4;      \
        CPA(_b + aw4, _Ap + _ao, szA);                                    \
        if (tid < 256) {                                                  \
            const size_t _bo = (size_t)brow * KW + _inr * 8 + ahalf * 4;  \
            CPA(_b + OFF_B + bw4, _Bp + _bo, 16);                         \
        }                                                                 \
        CPA_COMMIT();                                                     \
    } while (0)

    ISSUE_CHUNK(0, 0);
    ISSUE_CHUNK(1, 1);

    int s = 0;
    #pragma unroll 1
    for (int ch = 0; ch < NC3; ch++) {
        CPA_WAIT1();
        __syncthreads();
        // issue chunk ch+2 into the stage consumed at chunk ch-1 (safe: barrier above
        // orders all warps' chunk ch-1 ldmatrix reads before these writes)
        if (ch + 2 < NC3) {
            int s2 = s + 2; if (s2 >= 3) s2 -= 3;
            ISSUE_CHUNK(ch + 2, s2);
        }
        const uint32_t sb = sBase + (uint32_t)s * STG;

        uint32_t a[2][4], bb[8][2];
        LDM4(a[0][0], a[0][1], a[0][2], a[0][3], sb + aoff);
        LDM4(a[1][0], a[1][1], a[1][2], a[1][3], sb + aoff + 512);
        LDM4(bb[0][0], bb[0][1], bb[1][0], bb[1][1], sb + OFF_B + boff);
        LDM4(bb[2][0], bb[2][1], bb[3][0], bb[3][1], sb + OFF_B + boff + 512);
        LDM4(bb[4][0], bb[4][1], bb[5][0], bb[5][1], sb + OFF_B + boff + 1024);
        LDM4(bb[6][0], bb[6][1], bb[7][0], bb[7][1], sb + OFF_B + boff + 1536);

        #pragma unroll
        for (int mt = 0; mt < 2; mt++)
            #pragma unroll
            for (int nt = 0; nt < 8; nt++) mma16(acc[mt][nt], a[mt], bb[nt]);

        s = (s == 2) ? 0 : s + 1;
    }
#undef ISSUE_CHUNK

    // epilogue
    #pragma unroll
    for (int mt = 0; mt < 2; mt++) {
        const int r0 = m0 + wr * 32 + mt * 16 + g;
        const int r1 = r0 + 8;
        if (EPI == 0) {
            #pragma unroll
            for (int nt = 0; nt < 8; nt++) {
                const int col = wc * 64 + nt * 8 + tig * 2;
                if (r0 < NN)
                    *(float2*)&g_gbuf[(size_t)r0 * 128 + col] =
                        make_float2(acc[mt][nt][0], acc[mt][nt][1]);
                if (r1 < NN)
                    *(float2*)&g_gbuf[(size_t)r1 * 128 + col] =
                        make_float2(acc[mt][nt][2], acc[mt][nt][3]);
            }
        } else {
            #pragma unroll
            for (int nt = 0; nt < 8; nt++) {
                const int col = wc * 64 + nt * 8 + tig * 2;
                const float2 bv = *(const float2*)&bias_p[col];
                uint32_t h, l;
                if (r0 < NN) {
                    split2(fmaxf(acc[mt][nt][0] + bv.x, 0.f),
                           fmaxf(acc[mt][nt][1] + bv.y, 0.f), h, l);
                    g_x1h[r0 * 64 + (col >> 1)] = h;
                    g_x1l[r0 * 64 + (col >> 1)] = l;
                }
                if (r1 < NN) {
                    split2(fmaxf(acc[mt][nt][2] + bv.x, 0.f),
                           fmaxf(acc[mt][nt][3] + bv.y, 0.f), h, l);
                    g_x1h[r1 * 64 + (col >> 1)] = h;
                    g_x1l[r1 * 64 + (col >> 1)] = l;
                }
            }
        }
    }
}

// ---------------- classifier + log_softmax: warp per node (reads x1 planes) ----------------
__global__ void __launch_bounds__(256) k_out(const float* __restrict__ W,
                                             const float* __restrict__ bias,
                                             float* __restrict__ out) {
    __shared__ float ws[NCLS * 129];
    __shared__ float xs[8][128];
    __shared__ float bs[NCLS];
    int tid = threadIdx.x;
    for (int i = tid; i < NCLS * D; i += 256) {
        int c = i >> 7, k = i & 127;
        ws[c * 129 + k] = W[i];
    }
    if (tid < NCLS) bs[tid] = bias[tid];
    int w = tid >> 5, lane = tid & 31;
    int node = blockIdx.x * 8 + w;
    #pragma unroll
    for (int q = 0; q < 2; q++) {
        int idx = node * 64 + lane + 32 * q;
        uint32_t h = g_x1h[idx], l = g_x1l[idx];
        float v0 = __uint_as_float(h << 16) + __uint_as_float(l << 16);
        float v1 = __uint_as_float(h & 0xffff0000u) + __uint_as_float(l & 0xffff0000u);
        xs[w][2 * (lane + 32 * q)]     = v0;
        xs[w][2 * (lane + 32 * q) + 1] = v1;
    }
    __syncthreads();

    int c2 = 32 + (lane & 7);
    float acc0 = bs[lane];
    float acc1 = bs[c2];
    #pragma unroll 8
    for (int k = 0; k < D; k++) {
        float xv = xs[w][k];
        acc0 = fmaf(xv, ws[lane * 129 + k], acc0);
        acc1 = fmaf(xv, ws[c2 * 129 + k], acc1);
    }
    bool v1 = (lane < 8);
    float m = fmaxf(acc0, v1 ? acc1 : -1e30f);
    #pragma unroll
    for (int d = 16; d; d >>= 1) m = fmaxf(m, __shfl_xor_sync(0xffffffffu, m, d));
    float s = expf(acc0 - m) + (v1 ? expf(acc1 - m) : 0.f);
    #pragma unroll
    for (int d = 16; d; d >>= 1) s += __shfl_xor_sync(0xffffffffu, s, d);
    float lse = m + logf(s);
    out[node * NCLS + lane] = acc0 - lse;
    if (v1) out[node * NCLS + 32 + lane] = acc1 - lse;
}

// ---------------- launch ----------------
extern "C" void kernel_launch(void* const* d_in, const int* in_sizes, int n_in,
                              void* d_out, int out_size) {
    (void)in_sizes; (void)n_in; (void)out_size;
    const float* x    = (const float*)d_in[0];
    const int*   ei   = (const int*)d_in[1];
    const float* W0   = (const float*)d_in[2];
    const float* C0   = (const float*)d_in[3];
    const float* b0   = (const float*)d_in[4];
    const float* W1   = (const float*)d_in[5];
    const float* C1   = (const float*)d_in[6];
    const float* b1   = (const float*)d_in[7];
    const float* Wout = (const float*)d_in[8];
    const float* bout = (const float*)d_in[9];
    float* out = (float*)d_out;

    const int EB = (NE + 255) / 256;
    const int SXW = (NN * 64 + 128 * 64 + 255) / 256;

    k_init     <<<SCAN_NB, 256>>>();
    k_count    <<<EB, 256>>>(ei);
    k_split_xw0<<<SXW, 256>>>(x, W0);
    k_mma<128, 0, 0, 0><<<NT2, 640>>>(nullptr);   // h0 = x @ W0^T  [PROFILED]
    k_scan_a   <<<SCAN_NB, 256>>>();
    k_scan_b   <<<1, 256>>>();
    k_scan_c   <<<SCAN_NB, 256>>>();
    k_fill     <<<EB, 256>>>(ei);
    k_splitw<0><<<(128 * 256 + 255) / 256, 256>>>(C0, 128 * 256);
    k_splitw<1><<<(128 * 64 + 255) / 256, 256>>>(W1, 128 * 64);
    k_splitw<2><<<(128 * 256 + 255) / 256, 256>>>(C1, 128 * 256);

    // layer 0 aggregate + combine
    k_aggregate<<<NN / 8, 256>>>();
    k_mma<512, 2, 1, 1><<<NT2, 640>>>(b0);

    // layer 1
    k_mma<128, 0, 2, 2><<<NT2, 640>>>(nullptr);
    k_aggregate<<<NN / 8, 256>>>();
    k_mma<512, 2, 1, 3><<<NT2, 640>>>(b1);

    k_out<<<NN / 8, 256>>>(Wout, bout, out);
}